// round 8
// baseline (speedup 1.0000x reference)
#include <cuda_runtime.h>

#define TT 128
#define BB 512
#define QQ 50
#define BQ (BB * QQ)                 // 25600
#define NUNITS ((TT - 1) * BB)       // 65024
#define GAMMA_F 0.99f
#define NCH 8
#define CHL 16
#define UNITS 10                     // units per k_pairs block (10*25 = 250 thr)
#define RST 52                       // smem row stride, 16B aligned

// Per-chunk affine composites per chain: rets[chunk_lo] = A*rets[chunk_hi+1] + B
__device__ float2 g_AB[NCH * BQ];
// Discounted returns, row gu = t*BB+b at [gu*QQ .. gu*QQ+49], stored as float2.
__device__ float2 g_ret2[(TT - 1) * BQ / 2];

// ---------------------------------------------------------------------------
// Kernel 1: chunk composites. Thread = 2 q-adjacent chains (same b), chunk
// split into two independent 8-step halves for 2x MLP.  (~1.9 us measured)
// ---------------------------------------------------------------------------
__global__ __launch_bounds__(128)
void k_scan(const float* __restrict__ reward,
            const int*   __restrict__ step_type,
            const float* __restrict__ discount,
            const float* __restrict__ tvalue,
            float*       __restrict__ out)
{
    const int p = blockIdx.x * 128 + threadIdx.x;   // 0..12799 chain-pair
    const int c = blockIdx.y;
    if (c == 0 && p < BB) out[(TT - 1) * BB + p] = 0.0f;   // poisoned last row
    const int n = 2 * p;
    const int b = n / QQ;
    const int lo = c * CHL;
    const int hi = (c == NCH - 1) ? (TT - 2) : (lo + CHL - 1);

    float Au = 1.0f, Bu0 = 0.0f, Bu1 = 0.0f;
    float Al = 1.0f, Bl0 = 0.0f, Bl1 = 0.0f;
    #pragma unroll
    for (int k = 0; k < 8; ++k) {
        const int tu = hi - k;
        const int tl = lo + 7 - k;
        if (tu >= lo + 8) {
            float2 tv = *(const float2*)&tvalue[tu * BQ + n];
            int   il = step_type[tu * BB + b];
            float r  = reward[(tu + 1) * BB + b];
            float d  = discount[(tu + 1) * BB + b] * GAMMA_F;
            float a  = (il == 2) ? 0.0f : d;
            Au  = a * Au;
            Bu0 = fmaf(a, Bu0, (il == 2) ? tv.x : r);
            Bu1 = fmaf(a, Bu1, (il == 2) ? tv.y : r);
        }
        {
            float2 tv = *(const float2*)&tvalue[tl * BQ + n];
            int   il = step_type[tl * BB + b];
            float r  = reward[(tl + 1) * BB + b];
            float d  = discount[(tl + 1) * BB + b] * GAMMA_F;
            float a  = (il == 2) ? 0.0f : d;
            Al  = a * Al;
            Bl0 = fmaf(a, Bl0, (il == 2) ? tv.x : r);
            Bl1 = fmaf(a, Bl1, (il == 2) ? tv.y : r);
        }
    }
    g_AB[c * BQ + n]     = make_float2(Al * Au, fmaf(Al, Bu0, Bl0));
    g_AB[c * BQ + n + 1] = make_float2(Al * Au, fmaf(Al, Bu1, Bl1));
}

// ---------------------------------------------------------------------------
// Kernel 2: fill returns. Thread = 2 q-adjacent chains: compose tail-chunk
// composites (L2-hot) into the chunk seed, then walk CHL steps writing
// float2 returns.
// ---------------------------------------------------------------------------
__global__ __launch_bounds__(128)
void k_fill(const float* __restrict__ reward,
            const int*   __restrict__ step_type,
            const float* __restrict__ discount,
            const float* __restrict__ tvalue)
{
    const int p = blockIdx.x * 128 + threadIdx.x;   // 0..12799
    const int c = blockIdx.y;
    const int n = 2 * p;
    const int b = n / QQ;

    float2 cv = *(const float2*)&tvalue[(TT - 1) * BQ + n];   // rets[127]
    float c0 = cv.x, c1 = cv.y;
    #pragma unroll
    for (int cc = NCH - 1; cc > 0; --cc) {
        if (cc > c) {
            float2 ab0 = g_AB[cc * BQ + n];
            float2 ab1 = g_AB[cc * BQ + n + 1];
            c0 = fmaf(ab0.x, c0, ab0.y);
            c1 = fmaf(ab1.x, c1, ab1.y);
        }
    }
    // (c0,c1) == rets[hi+1] for this chunk

    const int lo = c * CHL;
    const int hi = (c == NCH - 1) ? (TT - 2) : (lo + CHL - 1);
    #pragma unroll
    for (int k = 0; k < CHL; ++k) {
        const int t = hi - k;
        if (t >= lo) {
            float2 tv = *(const float2*)&tvalue[t * BQ + n];
            int   il = step_type[t * BB + b];
            float r  = reward[(t + 1) * BB + b];
            float d  = discount[(t + 1) * BB + b] * GAMMA_F;
            float a  = (il == 2) ? 0.0f : d;
            c0 = fmaf(a, c0, (il == 2) ? tv.x : r);
            c1 = fmaf(a, c1, (il == 2) ? tv.y : r);
            g_ret2[(t * BQ + n) / 2] = make_float2(c0, c1);
        }
    }
}

// ---------------------------------------------------------------------------
// Kernel 3: pairwise quantile-Huber, one (u, j-pair) item per thread,
// one pass, fully unrolled. 10 units x 25 jp = 250 of 256 threads.
//   x = ret_i - v_j;  m = min(|x|,1);  c = (x&sign)|m;  t = x - 0.5c
//   h = c*t, sgn(x)*h = m*t ;  loss_j = 0.5*S + (tau_j-0.5)*D
// ---------------------------------------------------------------------------

#define PAIR2(r2_, nv2_, S2_, D2_) do {                                        \
    unsigned long long x2_, c2_, m2_, t2_;                                     \
    asm("add.rn.f32x2 %0, %1, %2;" : "=l"(x2_) : "l"(r2_), "l"(nv2_));         \
    float xl_, xh_;                                                            \
    asm("mov.b64 {%0, %1}, %2;" : "=f"(xl_), "=f"(xh_) : "l"(x2_));            \
    float ml_ = fminf(fabsf(xl_), 1.0f);                                       \
    float mh_ = fminf(fabsf(xh_), 1.0f);                                       \
    float cl_ = __int_as_float((__float_as_int(xl_) & 0x80000000) |            \
                               __float_as_int(ml_));                           \
    float ch_ = __int_as_float((__float_as_int(xh_) & 0x80000000) |            \
                               __float_as_int(mh_));                           \
    asm("mov.b64 %0, {%1, %2};" : "=l"(c2_) : "f"(cl_), "f"(ch_));             \
    asm("mov.b64 %0, {%1, %2};" : "=l"(m2_) : "f"(ml_), "f"(mh_));             \
    asm("fma.rn.f32x2 %0, %1, %2, %3;" : "=l"(t2_)                             \
        : "l"(c2_), "l"(MH2), "l"(x2_));                                       \
    asm("fma.rn.f32x2 %0, %1, %2, %0;" : "+l"(S2_) : "l"(c2_), "l"(t2_));      \
    asm("fma.rn.f32x2 %0, %1, %2, %0;" : "+l"(D2_) : "l"(m2_), "l"(t2_));      \
} while (0)

__global__ __launch_bounds__(256)
void k_pairs(const float* __restrict__ value,
             float*       __restrict__ out)
{
    __shared__ __align__(16) float s_ret[UNITS][RST];
    __shared__ float s_part[UNITS][QQ];

    const int tid = threadIdx.x;
    const int gu0 = blockIdx.x * UNITS;
    const int nu  = min(UNITS, NUNITS - gu0);

    const int u  = tid / 25;
    const int jp = tid - u * 25;

    // Stage: 250 float2 loads (g_ret rows gu0..gu0+nu-1 are gmem-contiguous).
    if (tid < UNITS * 25 && u < nu)
        ((float2*)&s_ret[u][0])[jp] = g_ret2[gu0 * (QQ / 2) + tid];
    __syncthreads();

    if (tid < UNITS * 25 && u < nu) {
        const int gu = gu0 + u;
        const float2 v2 = *(const float2*)&value[gu * QQ + 2 * jp];
        unsigned long long nv2a, nv2b;
        {
            float na = -v2.x, nb = -v2.y;
            asm("mov.b64 %0, {%1, %1};" : "=l"(nv2a) : "f"(na));
            asm("mov.b64 %0, {%1, %1};" : "=l"(nv2b) : "f"(nb));
        }
        const unsigned long long MH2 = 0xBF000000BF000000ULL;   // (-0.5,-0.5)
        unsigned long long S2a = 0, D2a = 0, S2b = 0, D2b = 0;

        const ulonglong2* rp2 = (const ulonglong2*)&s_ret[u][0];
        #pragma unroll
        for (int p = 0; p < 12; ++p) {               // 48 returns via LDS.128
            ulonglong2 rr = rp2[p];
            PAIR2(rr.x, nv2a, S2a, D2a);
            PAIR2(rr.x, nv2b, S2b, D2b);
            PAIR2(rr.y, nv2a, S2a, D2a);
            PAIR2(rr.y, nv2b, S2b, D2b);
        }
        {                                            // returns 48, 49
            unsigned long long rt_ = *(const unsigned long long*)&s_ret[u][48];
            PAIR2(rt_, nv2a, S2a, D2a);
            PAIR2(rt_, nv2b, S2b, D2b);
        }

        float sl, sh, dl, dh;
        asm("mov.b64 {%0, %1}, %2;" : "=f"(sl), "=f"(sh) : "l"(S2a));
        asm("mov.b64 {%0, %1}, %2;" : "=f"(dl), "=f"(dh) : "l"(D2a));
        const float taua = (2 * jp + 0.5f) * (1.0f / QQ);
        s_part[u][2 * jp]     = fmaf(taua - 0.5f, dl + dh, 0.5f * (sl + sh));

        asm("mov.b64 {%0, %1}, %2;" : "=f"(sl), "=f"(sh) : "l"(S2b));
        asm("mov.b64 {%0, %1}, %2;" : "=f"(dl), "=f"(dh) : "l"(D2b));
        const float taub = (2 * jp + 1.5f) * (1.0f / QQ);
        s_part[u][2 * jp + 1] = fmaf(taub - 0.5f, dl + dh, 0.5f * (sl + sh));
    }
    __syncthreads();

    // Deterministic fixed-order j-reduction, one thread per unit.
    if (tid < nu) {
        float s = 0.0f;
        #pragma unroll
        for (int j = 0; j < QQ; ++j) s += s_part[tid][j];
        out[gu0 + tid] = s * (1.0f / QQ);            // out idx t*BB+b == gu
    }
}

extern "C" void kernel_launch(void* const* d_in, const int* in_sizes, int n_in,
                              void* d_out, int out_size)
{
    const float* reward    = (const float*)d_in[0];
    const int*   step_type = (const int*)  d_in[1];
    const float* discount  = (const float*)d_in[2];
    const float* value     = (const float*)d_in[3];
    const float* tvalue    = (const float*)d_in[4];
    float*       out       = (float*)d_out;

    dim3 gs(BQ / 2 / 128, NCH);                      // (100, 8)
    k_scan<<<gs, 128>>>(reward, step_type, discount, tvalue, out);
    k_fill<<<gs, 128>>>(reward, step_type, discount, tvalue);

    const int nblocks = (NUNITS + UNITS - 1) / UNITS;   // 6503
    k_pairs<<<nblocks, 256>>>(value, out);
}